// round 15
// baseline (speedup 1.0000x reference)
#include <cuda_runtime.h>
#include <cuda_fp16.h>
#include <math.h>

#define FULLM 0xffffffffu
static const int NMAX = 100352;
static const int EMAX = 1700000;

// ---------------- device scratch ----------------
__device__ long long d_musum[256];
__device__ int      d_cnt[NMAX];
__device__ int      d_cur[NMAX];
__device__ int      d_off[NMAX + 1];
__device__ float    d_dinv[NMAX];
__device__ int      d_col[EMAX];
__device__ __align__(16) uint4 d_ga4[NMAX * 16];  // layer-0 cnt rows (fp16 exact), 256B rows
__device__ __align__(16) uint4 d_gb4[NMAX * 16];  // layer-1 cnt
__device__ __align__(16) uint4 d_g24[NMAX * 5];   // layer-2 cnt (40 feats, 80B rows)
__device__ __align__(16) unsigned d_wb0[8 * 128];
__device__ __align__(16) unsigned d_wb1[4 * 128];
__device__ __align__(16) unsigned d_wb2[4 * 40];
__device__ __align__(16) float d_al0[128];
__device__ __align__(16) float d_al1[128];
__device__ __align__(16) float d_al2[40];

__device__ __forceinline__ int detect64(const void* e) {
    const unsigned* w = (const unsigned*)e;
    int lane = threadIdx.x & 31;
    unsigned h0 = w[2 * lane + 1];
    unsigned h1 = w[64 + 2 * lane + 1];
    int z = __popc(__ballot_sync(FULLM, h0 == 0)) + __popc(__ballot_sync(FULLM, h1 == 0));
    return z >= 32;
}
__device__ __forceinline__ int ld_edge(const void* e, long long idx, int is64) {
    return is64 ? (int)((const long long*)e)[idx] : ((const int*)e)[idx];
}

// ============ L1: colsum partial | wprep | degree histogram (R7 exact) ============
__global__ void k_prep(const float* __restrict__ x,
                       const float* __restrict__ W0,
                       const float* __restrict__ W1,
                       const float* __restrict__ W2,
                       const void* __restrict__ e, long long E, int n) {
    int bid = blockIdx.x;
    if (bid < 512) {
        int rows = (n + 511) / 512;
        int r0 = bid * rows, r1 = min(n, r0 + rows);
        float s = 0.f;
        for (int r = r0; r < r1; r++) s += x[(long long)r * 256 + threadIdx.x];
        long long q = llrintf(s * 4194304.f);
        atomicAdd((unsigned long long*)&d_musum[threadIdx.x], (unsigned long long)q);
    } else if (bid < 549) {
        int W = (bid - 512) * 8 + (threadIdx.x >> 5);
        int lane = threadIdx.x & 31;
        const float* Wsrc; unsigned* wbT; float* alpha; int K, OUT, j;
        if (W < 128)      { Wsrc = W0; wbT = d_wb0; alpha = d_al0; K = 256; OUT = 128; j = W; }
        else if (W < 256) { Wsrc = W1; wbT = d_wb1; alpha = d_al1; K = 128; OUT = 128; j = W - 128; }
        else if (W < 296) { Wsrc = W2; wbT = d_wb2; alpha = d_al2; K = 128; OUT = 40;  j = W - 256; }
        else return;
        float s = 0.f;
        int KW = K / 32;
        for (int w = 0; w < KW; w++) {
            float v = Wsrc[(long long)(w * 32 + lane) * OUT + j];
            s += fabsf(v);
            unsigned m = __ballot_sync(FULLM, v > 0.f);
            if (lane == 0) wbT[w * OUT + j] = m;
        }
        for (int o = 16; o; o >>= 1) s += __shfl_xor_sync(FULLM, s, o);
        if (lane == 0) alpha[j] = s / (float)K;
    } else {
        int is64 = detect64(e);
        long long i = (long long)(bid - 549) * blockDim.x + threadIdx.x;
        if (i < E) atomicAdd(&d_cnt[ld_edge(e, E + i, is64)], 1);
    }
}

// ============ L2: fused bnpack + bmm0 | block-scan (R7 exact, writes d_ga4) ============
__global__ void k_bnpack_bmm0_scan(const float* __restrict__ x, int n, int wb64) {
    int bid = blockIdx.x;
    if (bid < wb64) {
        __shared__ float smu[256];
        smu[threadIdx.x] = (float)((double)d_musum[threadIdx.x] / (4194304.0 * (double)n));
        __syncthreads();
        int warp = threadIdx.x >> 5, lane = threadIdx.x & 31;
        uint2* ga2 = (uint2*)d_ga4;
        uint4 wv[8];
#pragma unroll
        for (int w = 0; w < 8; w++) wv[w] = *(const uint4*)&d_wb0[w * 128 + 4 * lane];
        int n0 = bid * 64 + warp * 8;
#pragma unroll
        for (int i = 0; i < 8; i++) {
            int node = n0 + i;
            if (node >= n) break;
            const float* xr = x + (long long)node * 256;
            unsigned bw[8];
#pragma unroll
            for (int w = 0; w < 8; w++) {
                float v = xr[w * 32 + lane];
                bw[w] = __ballot_sync(FULLM, v > smu[w * 32 + lane]);
            }
            int p0 = 0, p1 = 0, p2 = 0, p3 = 0;
#pragma unroll
            for (int w = 0; w < 8; w++) {
                p0 += __popc(bw[w] ^ wv[w].x);
                p1 += __popc(bw[w] ^ wv[w].y);
                p2 += __popc(bw[w] ^ wv[w].z);
                p3 += __popc(bw[w] ^ wv[w].w);
            }
            __half2 h0 = __floats2half2_rn((float)(256 - 2 * p0), (float)(256 - 2 * p1));
            __half2 h1 = __floats2half2_rn((float)(256 - 2 * p2), (float)(256 - 2 * p3));
            uint2 u;
            u.x = *(unsigned*)&h0;
            u.y = *(unsigned*)&h1;
            ga2[node * 32 + lane] = u;
        }
    } else {
        __shared__ int wsum[8];
        int t = threadIdx.x, lane = t & 31, wrp = t >> 5;
        int chunk = ((n + 255) / 256 + 3) & ~3;
        int c0 = t * chunk, c1 = min(n, c0 + chunk);
        int s = 0, i = c0;
        for (; i + 4 <= c1; i += 4) {
            int4 v = *(const int4*)(d_cnt + i);
            s += v.x + v.y + v.z + v.w;
        }
        for (; i < c1; i++) s += d_cnt[i];
        int incl = s;
        for (int o = 1; o < 32; o <<= 1) {
            int v = __shfl_up_sync(FULLM, incl, o);
            if (lane >= o) incl += v;
        }
        if (lane == 31) wsum[wrp] = incl;
        __syncthreads();
        if (wrp == 0) {
            int v = (lane < 8) ? wsum[lane] : 0;
            for (int o = 1; o < 8; o <<= 1) {
                int u = __shfl_up_sync(FULLM, v, o);
                if (lane >= o) v += u;
            }
            if (lane < 8) wsum[lane] = v;
        }
        __syncthreads();
        int run = incl - s + (wrp ? wsum[wrp - 1] : 0);
        for (i = c0; i < c1; i++) {
            int c = d_cnt[i];
            d_off[i] = run;
            run += c;
            d_dinv[i] = rsqrtf((float)(c + 1));
        }
        if (c0 < n && c1 == n) d_off[n] = run;
    }
}

// ============ L3: CSR fill (R7 exact) ============
__global__ void k_csr(const void* __restrict__ e, long long E) {
    int is64 = detect64(e);
    long long i = (long long)blockIdx.x * blockDim.x + threadIdx.x;
    if (i < E) {
        int sv = ld_edge(e, i, is64);
        int dv = ld_edge(e, E + i, is64);
        int pos = d_off[dv] + atomicAdd(&d_cur[dv], 1);
        d_col[pos] = sv;
    }
}

// accumulate 8 features from a uint4 (4 half2)
__device__ __forceinline__ void acc8(float4& A0, float4& A1, uint4 u, float s) {
    float2 f;
    f = __half22float2(*reinterpret_cast<__half2*>(&u.x)); A0.x += s * f.x; A0.y += s * f.y;
    f = __half22float2(*reinterpret_cast<__half2*>(&u.y)); A0.z += s * f.x; A0.w += s * f.y;
    f = __half22float2(*reinterpret_cast<__half2*>(&u.z)); A1.x += s * f.x; A1.y += s * f.y;
    f = __half22float2(*reinterpret_cast<__half2*>(&u.w)); A1.z += s * f.x; A1.w += s * f.y;
}

// paired gather: half-warps process even/odd items of the node's list
// (item 0 = self loop, items 1..deg = CSR edges). Row = RU uint4 per node.
template <int RU>
__device__ __forceinline__ void gatherP(const uint4* __restrict__ gp, int wid, int lane,
                                        float4& A0, float4& A1) {
    int li = lane & 15;
    int h = lane >> 4;
    int k0 = d_off[wid], k1 = d_off[wid + 1];
    int items = k1 - k0 + 1;
    A0 = make_float4(0.f, 0.f, 0.f, 0.f);
    A1 = A0;
    bool rowon = (li < RU);
    // peeled first item per half
    {
        int c = (h == 0) ? wid : ((items > 1) ? d_col[k0] : 0);
        bool on = (h == 0) || (items > 1);
        float s = on ? ((h == 0) ? d_dinv[wid] : d_dinv[c]) : 0.f;
        if (on && rowon) {
            uint4 u = gp[c * RU + li];
            acc8(A0, A1, u, s);
        }
    }
    int j = h + 2;
    for (; j + 2 < items; j += 4) {
        int c0 = d_col[k0 + j - 1];
        int c1 = d_col[k0 + j + 1];
        float s0 = d_dinv[c0], s1 = d_dinv[c1];
        if (rowon) {
            uint4 u0 = gp[c0 * RU + li];
            uint4 u1 = gp[c1 * RU + li];
            acc8(A0, A1, u0, s0);
            acc8(A0, A1, u1, s1);
        }
    }
    for (; j < items; j += 2) {
        int c = d_col[k0 + j - 1];
        float s = d_dinv[c];
        if (rowon) {
            uint4 u = gp[c * RU + li];
            acc8(A0, A1, u, s);
        }
    }
    // merge even/odd halves (result valid in all lanes)
    A0.x += __shfl_xor_sync(FULLM, A0.x, 16);
    A0.y += __shfl_xor_sync(FULLM, A0.y, 16);
    A0.z += __shfl_xor_sync(FULLM, A0.z, 16);
    A0.w += __shfl_xor_sync(FULLM, A0.w, 16);
    A1.x += __shfl_xor_sync(FULLM, A1.x, 16);
    A1.y += __shfl_xor_sync(FULLM, A1.y, 16);
    A1.z += __shfl_xor_sync(FULLM, A1.z, 16);
    A1.w += __shfl_xor_sync(FULLM, A1.w, 16);
}

// 8 sign bits per lane (feats 8*li..8*li+7) -> 4 broadcast 32-bit words
__device__ __forceinline__ void sign_words8(const float* v, int lane, unsigned bw[4]) {
    unsigned byte = 0;
#pragma unroll
    for (int i = 0; i < 8; i++) byte |= (unsigned)(v[i] > 0.f) << i;
    unsigned sh = byte << ((lane & 3) * 8);
    sh |= __shfl_xor_sync(FULLM, sh, 1);
    sh |= __shfl_xor_sync(FULLM, sh, 2);
#pragma unroll
    for (int w = 0; w < 4; w++) bw[w] = __shfl_sync(FULLM, sh, w * 4);
}

// ============ L4 (PROFILED): agg(layer-0) + sign + bmm1 -> d_gb4 ============
__global__ void __launch_bounds__(256) k_agg1_bmm1(const float* __restrict__ bias, int n) {
    int wid = (blockIdx.x * blockDim.x + threadIdx.x) >> 5;
    int lane = threadIdx.x & 31;
    if (wid >= n) return;
    float4 A0, A1;
    gatherP<16>(d_ga4, wid, lane, A0, A1);
    float di = d_dinv[wid];
    int li = lane & 15;
    float4 al0 = ((const float4*)d_al0)[2 * li];
    float4 al1 = ((const float4*)d_al0)[2 * li + 1];
    float4 b0  = ((const float4*)bias)[2 * li];
    float4 b1  = ((const float4*)bias)[2 * li + 1];
    float v[8];
    v[0] = A0.x * al0.x * di + b0.x;
    v[1] = A0.y * al0.y * di + b0.y;
    v[2] = A0.z * al0.z * di + b0.z;
    v[3] = A0.w * al0.w * di + b0.w;
    v[4] = A1.x * al1.x * di + b1.x;
    v[5] = A1.y * al1.y * di + b1.y;
    v[6] = A1.z * al1.z * di + b1.z;
    v[7] = A1.w * al1.w * di + b1.w;
    unsigned bw[4];
    sign_words8(v, lane, bw);
    uint4 wv[4];
#pragma unroll
    for (int w = 0; w < 4; w++) wv[w] = *(const uint4*)&d_wb1[w * 128 + 4 * lane];
    int p0 = 0, p1 = 0, p2 = 0, p3 = 0;
#pragma unroll
    for (int w = 0; w < 4; w++) {
        p0 += __popc(bw[w] ^ wv[w].x);
        p1 += __popc(bw[w] ^ wv[w].y);
        p2 += __popc(bw[w] ^ wv[w].z);
        p3 += __popc(bw[w] ^ wv[w].w);
    }
    __half2 h0 = __floats2half2_rn((float)(128 - 2 * p0), (float)(128 - 2 * p1));
    __half2 h1 = __floats2half2_rn((float)(128 - 2 * p2), (float)(128 - 2 * p3));
    uint2 u;
    u.x = *(unsigned*)&h0;
    u.y = *(unsigned*)&h1;
    ((uint2*)d_gb4)[wid * 32 + lane] = u;
}

// ============ L5: agg(layer-1) + sign + bmm2 -> d_g24 | re-zero scratch ============
__global__ void __launch_bounds__(256) k_agg2_bmm2(const float* __restrict__ bias, int n, int wpb) {
    if ((int)blockIdx.x >= wpb) {
        int b = blockIdx.x - wpb;
        for (int i = b * 256 + threadIdx.x; i < NMAX; i += 16 * 256) { d_cnt[i] = 0; d_cur[i] = 0; }
        if (b == 0 && threadIdx.x < 256) d_musum[threadIdx.x] = 0;
        return;
    }
    int wid = (blockIdx.x * blockDim.x + threadIdx.x) >> 5;
    int lane = threadIdx.x & 31;
    if (wid >= n) return;
    float4 A0, A1;
    gatherP<16>(d_gb4, wid, lane, A0, A1);
    float di = d_dinv[wid];
    int li = lane & 15;
    float4 al0 = ((const float4*)d_al1)[2 * li];
    float4 al1 = ((const float4*)d_al1)[2 * li + 1];
    float4 b0  = ((const float4*)bias)[2 * li];
    float4 b1  = ((const float4*)bias)[2 * li + 1];
    float v[8];
    v[0] = A0.x * al0.x * di + b0.x;
    v[1] = A0.y * al0.y * di + b0.y;
    v[2] = A0.z * al0.z * di + b0.z;
    v[3] = A0.w * al0.w * di + b0.w;
    v[4] = A1.x * al1.x * di + b1.x;
    v[5] = A1.y * al1.y * di + b1.y;
    v[6] = A1.z * al1.z * di + b1.z;
    v[7] = A1.w * al1.w * di + b1.w;
    unsigned bw[4];
    sign_words8(v, lane, bw);
    if (lane < 10) {
        uint4 wv[4];
#pragma unroll
        for (int w = 0; w < 4; w++) wv[w] = *(const uint4*)&d_wb2[w * 40 + 4 * lane];
        int p0 = 0, p1 = 0, p2 = 0, p3 = 0;
#pragma unroll
        for (int w = 0; w < 4; w++) {
            p0 += __popc(bw[w] ^ wv[w].x);
            p1 += __popc(bw[w] ^ wv[w].y);
            p2 += __popc(bw[w] ^ wv[w].z);
            p3 += __popc(bw[w] ^ wv[w].w);
        }
        __half2 h0 = __floats2half2_rn((float)(128 - 2 * p0), (float)(128 - 2 * p1));
        __half2 h1 = __floats2half2_rn((float)(128 - 2 * p2), (float)(128 - 2 * p3));
        uint2 u;
        u.x = *(unsigned*)&h0;
        u.y = *(unsigned*)&h1;
        ((uint2*)d_g24)[wid * 10 + lane] = u;
    }
}

// ============ L6: final agg (40 feats, paired) + bias + log_softmax ============
__global__ void __launch_bounds__(256) k_agg_out(const float* __restrict__ bias,
                                                 float* __restrict__ out, int n) {
    int wid = (blockIdx.x * blockDim.x + threadIdx.x) >> 5;
    int lane = threadIdx.x & 31;
    if (wid >= n) return;
    float4 A0, A1;
    gatherP<5>(d_g24, wid, lane, A0, A1);
    float di = d_dinv[wid];
    int li = lane & 15;
    bool act = li < 5;
    float v[8];
#pragma unroll
    for (int i = 0; i < 8; i++) v[i] = -1e30f;
    if (act) {
        float4 al0 = ((const float4*)d_al2)[2 * li];
        float4 al1 = ((const float4*)d_al2)[2 * li + 1];
        float4 b0  = ((const float4*)bias)[2 * li];
        float4 b1  = ((const float4*)bias)[2 * li + 1];
        v[0] = A0.x * al0.x * di + b0.x;
        v[1] = A0.y * al0.y * di + b0.y;
        v[2] = A0.z * al0.z * di + b0.z;
        v[3] = A0.w * al0.w * di + b0.w;
        v[4] = A1.x * al1.x * di + b1.x;
        v[5] = A1.y * al1.y * di + b1.y;
        v[6] = A1.z * al1.z * di + b1.z;
        v[7] = A1.w * al1.w * di + b1.w;
    }
    float m = v[0];
#pragma unroll
    for (int i = 1; i < 8; i++) m = fmaxf(m, v[i]);
    for (int o = 16; o; o >>= 1) m = fmaxf(m, __shfl_xor_sync(FULLM, m, o));
    float se = 0.f;
    if (act) {
#pragma unroll
        for (int i = 0; i < 8; i++) se += expf(v[i] - m);
    }
    for (int o = 16; o; o >>= 1) se += __shfl_xor_sync(FULLM, se, o);
    float lse = logf(se * 0.5f);    // both halves contribute duplicates -> halve
    if (act && lane < 16) {
        float4 r0, r1;
        r0.x = v[0] - m - lse; r0.y = v[1] - m - lse;
        r0.z = v[2] - m - lse; r0.w = v[3] - m - lse;
        r1.x = v[4] - m - lse; r1.y = v[5] - m - lse;
        r1.z = v[6] - m - lse; r1.w = v[7] - m - lse;
        float4* op = (float4*)(out + (long long)wid * 40 + li * 8);
        op[0] = r0;
        op[1] = r1;
    }
}

// ---------------- launch ----------------
extern "C" void kernel_launch(void* const* d_in, const int* in_sizes, int n_in,
                              void* d_out, int out_size) {
    const float* x  = (const float*)d_in[0];
    const void*  ei = d_in[1];
    const float* b0 = (const float*)d_in[3];
    const float* b1 = (const float*)d_in[5];
    const float* b2 = (const float*)d_in[7];
    float* out = (float*)d_out;

    int N = in_sizes[0] / 256;
    long long E = (long long)in_sizes[1] / 2;

    int eb   = (int)((E + 255) / 256);
    int wb64 = (N + 63) / 64;
    int wpb  = (N + 7) / 8;

    k_prep<<<549 + eb, 256>>>(x, (const float*)d_in[2], (const float*)d_in[4],
                              (const float*)d_in[6], ei, E, N);   // 1
    k_bnpack_bmm0_scan<<<wb64 + 1, 256>>>(x, N, wb64);            // 2
    k_csr<<<eb, 256>>>(ei, E);                                    // 3
    k_agg1_bmm1<<<wpb, 256>>>(b0, N);                             // 4 (PROFILED)
    k_agg2_bmm2<<<wpb + 16, 256>>>(b1, N, wpb);                   // 5
    k_agg_out<<<wpb, 256>>>(b2, out, N);                          // 6
}

// round 16
// speedup vs baseline: 1.0888x; 1.0888x over previous
#include <cuda_runtime.h>
#include <cuda_fp16.h>
#include <math.h>

#define FULLM 0xffffffffu
static const int NMAX = 100352;
static const int EMAX = 1700000;

// ---------------- device scratch ----------------
__device__ long long d_musum[256];
__device__ int      d_flag;
__device__ int      d_cnt[NMAX];
__device__ int      d_cur[NMAX];
__device__ int      d_off[NMAX + 1];
__device__ float    d_dinv[NMAX];
__device__ int      d_col[EMAX];
__device__ uint2    d_ga[NMAX * 32];   // layer-0 cnt (fp16 exact)
__device__ uint2    d_gb[NMAX * 32];   // layer-1 cnt
__device__ uint2    d_g2[NMAX * 10];   // layer-2 cnt (40 feats)
__device__ __align__(16) unsigned d_wb0[8 * 128];
__device__ __align__(16) unsigned d_wb1[4 * 128];
__device__ __align__(16) unsigned d_wb2[4 * 40];
__device__ __align__(16) float d_al0[128];
__device__ __align__(16) float d_al1[128];
__device__ __align__(16) float d_al2[40];

__device__ __forceinline__ int detect64(const void* e) {
    const unsigned* w = (const unsigned*)e;
    int lane = threadIdx.x & 31;
    unsigned h0 = w[2 * lane + 1];
    unsigned h1 = w[64 + 2 * lane + 1];
    int z = __popc(__ballot_sync(FULLM, h0 == 0)) + __popc(__ballot_sync(FULLM, h1 == 0));
    return z >= 32;
}
__device__ __forceinline__ int ld_edge(const void* e, long long idx, int is64) {
    return is64 ? (int)((const long long*)e)[idx] : ((const int*)e)[idx];
}

// ============ L1: colsum partial | wprep | degree histogram (R7 exact) ============
__global__ void k_prep(const float* __restrict__ x,
                       const float* __restrict__ W0,
                       const float* __restrict__ W1,
                       const float* __restrict__ W2,
                       const void* __restrict__ e, long long E, int n) {
    int bid = blockIdx.x;
    if (bid < 512) {
        int rows = (n + 511) / 512;
        int r0 = bid * rows, r1 = min(n, r0 + rows);
        float s = 0.f;
        for (int r = r0; r < r1; r++) s += x[(long long)r * 256 + threadIdx.x];
        long long q = llrintf(s * 4194304.f);
        atomicAdd((unsigned long long*)&d_musum[threadIdx.x], (unsigned long long)q);
    } else if (bid < 549) {
        int W = (bid - 512) * 8 + (threadIdx.x >> 5);
        int lane = threadIdx.x & 31;
        const float* Wsrc; unsigned* wbT; float* alpha; int K, OUT, j;
        if (W < 128)      { Wsrc = W0; wbT = d_wb0; alpha = d_al0; K = 256; OUT = 128; j = W; }
        else if (W < 256) { Wsrc = W1; wbT = d_wb1; alpha = d_al1; K = 128; OUT = 128; j = W - 128; }
        else if (W < 296) { Wsrc = W2; wbT = d_wb2; alpha = d_al2; K = 128; OUT = 40;  j = W - 256; }
        else return;
        float s = 0.f;
        int KW = K / 32;
        for (int w = 0; w < KW; w++) {
            float v = Wsrc[(long long)(w * 32 + lane) * OUT + j];
            s += fabsf(v);
            unsigned m = __ballot_sync(FULLM, v > 0.f);
            if (lane == 0) wbT[w * OUT + j] = m;
        }
        for (int o = 16; o; o >>= 1) s += __shfl_xor_sync(FULLM, s, o);
        if (lane == 0) alpha[j] = s / (float)K;
    } else {
        int is64 = detect64(e);
        long long i = (long long)(bid - 549) * blockDim.x + threadIdx.x;
        if (i < E) atomicAdd(&d_cnt[ld_edge(e, E + i, is64)], 1);
    }
}

// ============ L2: scan (block 0) | bnpack+bmm0 (1..wb64) | csr (spin on flag) ============
__global__ void __launch_bounds__(256) k_pipe2(const float* __restrict__ x,
                                               const void* __restrict__ e,
                                               long long E, int n, int wb64) {
    int bid = blockIdx.x;
    if (bid == 0) {
        // exclusive scan of d_cnt -> d_off; dinv; then release flag (wave-1 guaranteed)
        __shared__ int wsum[8];
        int t = threadIdx.x, lane = t & 31, wrp = t >> 5;
        int chunk = ((n + 255) / 256 + 3) & ~3;
        int c0 = t * chunk, c1 = min(n, c0 + chunk);
        int s = 0, i = c0;
        for (; i + 4 <= c1; i += 4) {
            int4 v = *(const int4*)(d_cnt + i);
            s += v.x + v.y + v.z + v.w;
        }
        for (; i < c1; i++) s += d_cnt[i];
        int incl = s;
        for (int o = 1; o < 32; o <<= 1) {
            int v = __shfl_up_sync(FULLM, incl, o);
            if (lane >= o) incl += v;
        }
        if (lane == 31) wsum[wrp] = incl;
        __syncthreads();
        if (wrp == 0) {
            int v = (lane < 8) ? wsum[lane] : 0;
            for (int o = 1; o < 8; o <<= 1) {
                int u = __shfl_up_sync(FULLM, v, o);
                if (lane >= o) v += u;
            }
            if (lane < 8) wsum[lane] = v;
        }
        __syncthreads();
        int run = incl - s + (wrp ? wsum[wrp - 1] : 0);
        for (i = c0; i < c1; i++) {
            int c = d_cnt[i];
            d_off[i] = run;
            run += c;
            d_dinv[i] = rsqrtf((float)(c + 1));
        }
        if (c0 < n && c1 == n) d_off[n] = run;
        __threadfence();
        __syncthreads();
        if (t == 0) atomicExch(&d_flag, 1);
    } else if (bid <= wb64) {
        // BN threshold + sign bitpack + bmm0, bits in regs (R7 exact body)
        __shared__ float smu[256];
        smu[threadIdx.x] = (float)((double)d_musum[threadIdx.x] / (4194304.0 * (double)n));
        __syncthreads();
        int warp = threadIdx.x >> 5, lane = threadIdx.x & 31;
        uint4 wv[8];
#pragma unroll
        for (int w = 0; w < 8; w++) wv[w] = *(const uint4*)&d_wb0[w * 128 + 4 * lane];
        int n0 = (bid - 1) * 64 + warp * 8;
#pragma unroll
        for (int i = 0; i < 8; i++) {
            int node = n0 + i;
            if (node >= n) break;
            const float* xr = x + (long long)node * 256;
            unsigned bw[8];
#pragma unroll
            for (int w = 0; w < 8; w++) {
                float v = xr[w * 32 + lane];
                bw[w] = __ballot_sync(FULLM, v > smu[w * 32 + lane]);
            }
            int p0 = 0, p1 = 0, p2 = 0, p3 = 0;
#pragma unroll
            for (int w = 0; w < 8; w++) {
                p0 += __popc(bw[w] ^ wv[w].x);
                p1 += __popc(bw[w] ^ wv[w].y);
                p2 += __popc(bw[w] ^ wv[w].z);
                p3 += __popc(bw[w] ^ wv[w].w);
            }
            __half2 h0 = __floats2half2_rn((float)(256 - 2 * p0), (float)(256 - 2 * p1));
            __half2 h1 = __floats2half2_rn((float)(256 - 2 * p2), (float)(256 - 2 * p3));
            uint2 u;
            u.x = *(unsigned*)&h0;
            u.y = *(unsigned*)&h1;
            d_ga[node * 32 + lane] = u;
        }
    } else {
        // CSR fill: prefetch edge, wait for scan flag (already set for tail waves), place
        int is64 = detect64(e);
        long long i = (long long)(bid - wb64 - 1) * blockDim.x + threadIdx.x;
        int sv = 0, dv = 0;
        bool act = (i < E);
        if (act) {
            sv = ld_edge(e, i, is64);
            dv = ld_edge(e, E + i, is64);
        }
        if (threadIdx.x == 0) {
            while (atomicAdd(&d_flag, 0) == 0) __nanosleep(128);
            __threadfence();
        }
        __syncthreads();
        if (act) {
            int pos = d_off[dv] + atomicAdd(&d_cur[dv], 1);
            d_col[pos] = sv;
        }
    }
}

__device__ __forceinline__ void accH(float4& a, uint2 u, float s) {
    float2 f0 = __half22float2(*reinterpret_cast<__half2*>(&u.x));
    float2 f1 = __half22float2(*reinterpret_cast<__half2*>(&u.y));
    a.x += s * f0.x; a.y += s * f0.y; a.z += s * f1.x; a.w += s * f1.y;
}

// gather body over CSR (R7 frozen version, 32 regs, 81% occ)
__device__ __forceinline__ float4 gather128(const uint2* __restrict__ gp, int wid, int lane) {
    float4 A = make_float4(0.f, 0.f, 0.f, 0.f), B = A;
    accH(A, gp[(long long)wid * 32 + lane], d_dinv[wid]);   // self loop
    int k = d_off[wid], k1 = d_off[wid + 1];
    for (; k + 8 <= k1; k += 8) {
        int c[8]; float s[8]; uint2 u[8];
#pragma unroll
        for (int j = 0; j < 8; j++) c[j] = d_col[k + j];
#pragma unroll
        for (int j = 0; j < 8; j++) s[j] = d_dinv[c[j]];
#pragma unroll
        for (int j = 0; j < 8; j++) u[j] = gp[c[j] * 32 + lane];
#pragma unroll
        for (int j = 0; j < 8; j++) accH((j & 1) ? B : A, u[j], s[j]);
    }
    if (k + 4 <= k1) {
        int c[4]; float s[4]; uint2 u[4];
#pragma unroll
        for (int j = 0; j < 4; j++) c[j] = d_col[k + j];
#pragma unroll
        for (int j = 0; j < 4; j++) s[j] = d_dinv[c[j]];
#pragma unroll
        for (int j = 0; j < 4; j++) u[j] = gp[c[j] * 32 + lane];
#pragma unroll
        for (int j = 0; j < 4; j++) accH((j & 1) ? B : A, u[j], s[j]);
        k += 4;
    }
    for (; k < k1; k++) {
        int c = d_col[k];
        accH(B, gp[c * 32 + lane], d_dinv[c]);
    }
    A.x += B.x; A.y += B.y; A.z += B.z; A.w += B.w;
    return A;
}

__device__ __forceinline__ void sign_words(float v0, float v1, float v2, float v3,
                                           int lane, unsigned bw[4]) {
    unsigned nib = (unsigned)(v0 > 0.f) | ((unsigned)(v1 > 0.f) << 1) |
                   ((unsigned)(v2 > 0.f) << 2) | ((unsigned)(v3 > 0.f) << 3);
    unsigned sh = nib << ((lane & 7) * 4);
    sh |= __shfl_xor_sync(FULLM, sh, 1);
    sh |= __shfl_xor_sync(FULLM, sh, 2);
    sh |= __shfl_xor_sync(FULLM, sh, 4);
#pragma unroll
    for (int wd = 0; wd < 4; wd++) bw[wd] = __shfl_sync(FULLM, sh, wd * 8);
}

// ============ L3: agg(layer-0) + sign + bmm1 -> d_gb (R7 exact) ============
__global__ void k_agg1_bmm1(const float* __restrict__ bias, int n) {
    int wid = (blockIdx.x * blockDim.x + threadIdx.x) >> 5;
    int lane = threadIdx.x & 31;
    if (wid >= n) return;
    float4 A = gather128(d_ga, wid, lane);
    float di = d_dinv[wid];
    float4 al = ((const float4*)d_al0)[lane];
    float4 b  = ((const float4*)bias)[lane];
    float v0 = A.x * al.x * di + b.x;
    float v1 = A.y * al.y * di + b.y;
    float v2 = A.z * al.z * di + b.z;
    float v3 = A.w * al.w * di + b.w;
    unsigned bw[4];
    sign_words(v0, v1, v2, v3, lane, bw);
    uint4 wv[4];
#pragma unroll
    for (int w = 0; w < 4; w++) wv[w] = *(const uint4*)&d_wb1[w * 128 + 4 * lane];
    int p0 = 0, p1 = 0, p2 = 0, p3 = 0;
#pragma unroll
    for (int w = 0; w < 4; w++) {
        p0 += __popc(bw[w] ^ wv[w].x);
        p1 += __popc(bw[w] ^ wv[w].y);
        p2 += __popc(bw[w] ^ wv[w].z);
        p3 += __popc(bw[w] ^ wv[w].w);
    }
    __half2 h0 = __floats2half2_rn((float)(128 - 2 * p0), (float)(128 - 2 * p1));
    __half2 h1 = __floats2half2_rn((float)(128 - 2 * p2), (float)(128 - 2 * p3));
    uint2 u;
    u.x = *(unsigned*)&h0;
    u.y = *(unsigned*)&h1;
    d_gb[wid * 32 + lane] = u;
}

// ============ L4 (PROFILED): agg(layer-1) + sign + bmm2 -> d_g2 | re-zero ============
__global__ void k_agg2_bmm2(const float* __restrict__ bias, int n, int wpb) {
    if ((int)blockIdx.x >= wpb) {
        int b = blockIdx.x - wpb;
        for (int i = b * 256 + threadIdx.x; i < NMAX; i += 16 * 256) { d_cnt[i] = 0; d_cur[i] = 0; }
        if (b == 0) {
            if (threadIdx.x < 256) d_musum[threadIdx.x] = 0;
            if (threadIdx.x == 0) d_flag = 0;
        }
        return;
    }
    int wid = (blockIdx.x * blockDim.x + threadIdx.x) >> 5;
    int lane = threadIdx.x & 31;
    if (wid >= n) return;
    float4 A = gather128(d_gb, wid, lane);
    float di = d_dinv[wid];
    float4 al = ((const float4*)d_al1)[lane];
    float4 b  = ((const float4*)bias)[lane];
    float v0 = A.x * al.x * di + b.x;
    float v1 = A.y * al.y * di + b.y;
    float v2 = A.z * al.z * di + b.z;
    float v3 = A.w * al.w * di + b.w;
    unsigned bw[4];
    sign_words(v0, v1, v2, v3, lane, bw);
    if (lane < 10) {
        uint4 wv[4];
#pragma unroll
        for (int w = 0; w < 4; w++) wv[w] = *(const uint4*)&d_wb2[w * 40 + 4 * lane];
        int p0 = 0, p1 = 0, p2 = 0, p3 = 0;
#pragma unroll
        for (int w = 0; w < 4; w++) {
            p0 += __popc(bw[w] ^ wv[w].x);
            p1 += __popc(bw[w] ^ wv[w].y);
            p2 += __popc(bw[w] ^ wv[w].z);
            p3 += __popc(bw[w] ^ wv[w].w);
        }
        __half2 h0 = __floats2half2_rn((float)(128 - 2 * p0), (float)(128 - 2 * p1));
        __half2 h1 = __floats2half2_rn((float)(128 - 2 * p2), (float)(128 - 2 * p3));
        uint2 u;
        u.x = *(unsigned*)&h0;
        u.y = *(unsigned*)&h1;
        d_g2[wid * 10 + lane] = u;
    }
}

// ============ L5: final aggregation (40 feats) + bias + log_softmax (R7 exact) ============
__global__ void k_agg_out(const float* __restrict__ bias, float* __restrict__ out, int n) {
    int wid = (blockIdx.x * blockDim.x + threadIdx.x) >> 5;
    int lane = threadIdx.x & 31;
    if (wid >= n) return;
    const __half2* gh = (const __half2*)d_g2;
    bool act = lane < 20;
    float di = d_dinv[wid];
    float2 A = make_float2(0.f, 0.f), B = A;
    if (act) {
        float2 f = __half22float2(gh[(long long)wid * 20 + lane]);
        A.x += di * f.x; A.y += di * f.y;
    }
    int k = d_off[wid], k1 = d_off[wid + 1];
    for (; k + 8 <= k1; k += 8) {
        int c[8]; float s[8]; float2 f[8];
#pragma unroll
        for (int j = 0; j < 8; j++) c[j] = d_col[k + j];
#pragma unroll
        for (int j = 0; j < 8; j++) s[j] = d_dinv[c[j]];
        if (act) {
#pragma unroll
            for (int j = 0; j < 8; j++) f[j] = __half22float2(gh[c[j] * 20 + lane]);
#pragma unroll
            for (int j = 0; j < 8; j++) {
                if (j & 1) { B.x += s[j] * f[j].x; B.y += s[j] * f[j].y; }
                else       { A.x += s[j] * f[j].x; A.y += s[j] * f[j].y; }
            }
        }
    }
    for (; k < k1; k++) {
        int c = d_col[k];
        float s = d_dinv[c];
        if (act) {
            float2 f = __half22float2(gh[c * 20 + lane]);
            B.x += s * f.x; B.y += s * f.y;
        }
    }
    float v0 = -1e30f, v1 = -1e30f;
    if (act) {
        float2 al = ((const float2*)d_al2)[lane];
        float2 b  = ((const float2*)bias)[lane];
        v0 = (A.x + B.x) * al.x * di + b.x;
        v1 = (A.y + B.y) * al.y * di + b.y;
    }
    float m = fmaxf(v0, v1);
    for (int o = 16; o; o >>= 1) m = fmaxf(m, __shfl_xor_sync(FULLM, m, o));
    float se = act ? (expf(v0 - m) + expf(v1 - m)) : 0.f;
    for (int o = 16; o; o >>= 1) se += __shfl_xor_sync(FULLM, se, o);
    float lse = logf(se);
    if (act) {
        float2 r;
        r.x = v0 - m - lse;
        r.y = v1 - m - lse;
        ((float2*)out)[wid * 20 + lane] = r;
    }
}

// ---------------- launch ----------------
extern "C" void kernel_launch(void* const* d_in, const int* in_sizes, int n_in,
                              void* d_out, int out_size) {
    const float* x  = (const float*)d_in[0];
    const void*  ei = d_in[1];
    const float* b0 = (const float*)d_in[3];
    const float* b1 = (const float*)d_in[5];
    const float* b2 = (const float*)d_in[7];
    float* out = (float*)d_out;

    int N = in_sizes[0] / 256;
    long long E = (long long)in_sizes[1] / 2;

    int eb   = (int)((E + 255) / 256);
    int wb64 = (N + 63) / 64;
    int wpb  = (N + 7) / 8;

    k_prep<<<549 + eb, 256>>>(x, (const float*)d_in[2], (const float*)d_in[4],
                              (const float*)d_in[6], ei, E, N);   // 1
    k_pipe2<<<1 + wb64 + eb, 256>>>(x, ei, E, N, wb64);           // 2: scan|bnpack+bmm0|csr
    k_agg1_bmm1<<<wpb, 256>>>(b0, N);                             // 3
    k_agg2_bmm2<<<wpb + 16, 256>>>(b1, N, wpb);                   // 4 (PROFILED)
    k_agg_out<<<wpb, 256>>>(b2, out, N);                          // 5
}